// round 9
// baseline (speedup 1.0000x reference)
#include <cuda_runtime.h>
#include <math.h>

// Problem constants (fixed by reference setup_inputs)
#define BB 4
#define HH 8
#define SS 2048
#define DD 8
#define CAP 32
#define VERIFY_BLOCKS 32
#define M0 0.015f                 // speculative margin; verified in k_verify

// Scratch. g_xn2 is a monotone max over fixed inputs (same value every call).
// g_nrare (overflow rows, cnt > CAP) is reset by the last k_verify block.
__device__ unsigned g_xn2;
__device__ int      g_nrare;
__device__ int      g_done2;
__device__ int      g_rlist[BB*SS];

// ---------------------------------------------------------------------------
// Block-level handler for rows with 2 <= cnt <= CAP. Called by all 256
// threads of a k_scan block; __noinline__ keeps its registers out of the
// hot streaming path. Warp w = head w; lane i = candidate i. Exact softmax
// over the candidate set (excluded keys carry < e^-30 relative weight,
// guaranteed by the margin verified in k_verify).
// ---------------------------------------------------------------------------
__device__ __noinline__ void rare_block(
        const float* __restrict__ x,
        const float* __restrict__ Wq, const float* __restrict__ bq,
        const float* __restrict__ Wk, const float* __restrict__ bk,
        float* __restrict__ out,
        int b, int q, int cnt, const int* s_idx, const float* s_mv) {
    int t    = threadIdx.x;
    int w    = t >> 5;
    int lane = t & 31;
    int bh   = b * HH + w;
    const float* xb = x + (size_t)bh * SS * DD;

    // q projection (identical on all lanes of the warp; broadcast loads)
    const float4* xq = (const float4*)(xb + (size_t)q * DD);
    float4 a0 = xq[0], a1 = xq[1];
    float xv[8] = {a0.x, a0.y, a0.z, a0.w, a1.x, a1.y, a1.z, a1.w};
    float qv[8];
#pragma unroll
    for (int i = 0; i < 8; i++) {
        float s = __ldg(bq + i);
#pragma unroll
        for (int j = 0; j < 8; j++) s += xv[j] * __ldg(Wq + i*8 + j);
        qv[i] = s;
    }

    float score = -INFINITY;
    float xk[8] = {0,0,0,0,0,0,0,0};
    if (lane < cnt) {
        int kk = s_idx[lane];
        const float4* xr = (const float4*)(xb + (size_t)kk * DD);
        float4 c0 = xr[0], c1 = xr[1];
        xk[0]=c0.x; xk[1]=c0.y; xk[2]=c0.z; xk[3]=c0.w;
        xk[4]=c1.x; xk[5]=c1.y; xk[6]=c1.z; xk[7]=c1.w;
        float sdot = 0.f;
#pragma unroll
        for (int i = 0; i < 8; i++) {
            float kv = __ldg(bk + i);
#pragma unroll
            for (int j = 0; j < 8; j++) kv += xk[j] * __ldg(Wk + i*8 + j);
            sdot += qv[i] * kv;
        }
        score = sdot * 0.35355339059f - 10000.0f * s_mv[lane];
    }

    float m = score;
#pragma unroll
    for (int o = 16; o; o >>= 1) m = fmaxf(m, __shfl_xor_sync(0xffffffffu, m, o));
    float p = (lane < cnt) ? expf(score - m) : 0.f;
    float l = p;
#pragma unroll
    for (int o = 16; o; o >>= 1) l += __shfl_xor_sync(0xffffffffu, l, o);
    float acc[8];
#pragma unroll
    for (int i = 0; i < 8; i++) {
        float s = p * xk[i];
#pragma unroll
        for (int o = 16; o; o >>= 1) s += __shfl_xor_sync(0xffffffffu, s, o);
        acc[i] = s;
    }
    if (lane == 0) {
        float inv = 1.0f / l;
        float4* o = (float4*)(out + ((size_t)bh * SS + q) * DD);
        o[0] = make_float4(acc[0]*inv, acc[1]*inv, acc[2]*inv, acc[3]*inv);
        o[1] = make_float4(acc[4]*inv, acc[5]*inv, acc[6]*inv, acc[7]*inv);
    }
}

// ---------------------------------------------------------------------------
// Kernel 1: lean mask-row scan + full row resolution. Block per (b,q) row.
// Streams the 64 MB mask exactly once, with an x-norm side-task (8 x-rows
// per block -> atomicMax into g_xn2, complete by kernel end).
// cnt==1 (~96%): softmax weight is exactly 1 -> copy x row for all 8 heads.
// 2<=cnt<=CAP (~4%): resolved in-block by rare_block.
// cnt>CAP (never observed): spilled to g_rlist for k_verify.
// ---------------------------------------------------------------------------
__global__ void __launch_bounds__(256) k_scan(
        const float* __restrict__ x, const float* __restrict__ mask,
        const float* __restrict__ Wq, const float* __restrict__ bq,
        const float* __restrict__ Wk, const float* __restrict__ bk,
        float* __restrict__ out) {
    int row = blockIdx.x;               // b*SS + q
    int b   = row >> 11;
    int q   = row & (SS - 1);
    int t   = threadIdx.x;

    __shared__ float warpmin[8];
    __shared__ float s_thresh;
    __shared__ int   s_cnt;
    __shared__ int   s_idx[CAP];
    __shared__ float s_mv[CAP];

    const float4* mr = (const float4*)(mask + (size_t)row * SS);
    float4 m0 = mr[t * 2], m1 = mr[t * 2 + 1];

    // side-task: x-norm partials (rows 8*blockIdx .. +8), 16 threads, 4 floats each
    float xn = 0.f;
    if (t < 16) {
        int xrow = blockIdx.x * 8 + (t >> 1);
        const float4* xr = (const float4*)(x + (size_t)xrow * DD) + (t & 1);
        float4 a = *xr;
        xn = a.x*a.x + a.y*a.y + a.z*a.z + a.w*a.w;
    }

    float v[8] = {m0.x, m0.y, m0.z, m0.w, m1.x, m1.y, m1.z, m1.w};
    float mn = v[0];
#pragma unroll
    for (int j = 1; j < 8; j++) mn = fminf(mn, v[j]);
#pragma unroll
    for (int o = 16; o; o >>= 1) mn = fminf(mn, __shfl_xor_sync(0xffffffffu, mn, o));
    if ((t & 31) == 0) warpmin[t >> 5] = mn;

    if (t < 32) {    // warp 0 finishes the x-norm side reduction
#pragma unroll
        for (int o = 8; o; o >>= 1) xn = fmaxf(xn, __shfl_xor_sync(0xffffffffu, xn, o));
        if (t == 0) atomicMax(&g_xn2, __float_as_uint(xn));   // xn>=0: uint==float order
    }
    __syncthreads();
    if (t == 0) {
        float m = fminf(fminf(fminf(warpmin[0], warpmin[1]), fminf(warpmin[2], warpmin[3])),
                        fminf(fminf(warpmin[4], warpmin[5]), fminf(warpmin[6], warpmin[7])));
        s_thresh = m + M0;
        s_cnt = 0;
    }
    __syncthreads();

    float th = s_thresh;
#pragma unroll
    for (int j = 0; j < 8; j++) {
        if (v[j] <= th) {
            int p = atomicAdd(&s_cnt, 1);
            if (p < CAP) { s_idx[p] = t * 8 + j; s_mv[p] = v[j]; }
        }
    }
    __syncthreads();

    int cnt = s_cnt;
    if (cnt == 1) {
        if (t < 16) {
            int h = t >> 1, p = t & 1;
            int kk = s_idx[0];
            size_t base = ((size_t)(b * HH + h) * SS);
            const float4* src = (const float4*)(x   + (base + kk) * DD);
            float4*       dst = (float4*)      (out + (base + q ) * DD);
            dst[p] = src[p];
        }
    } else if (cnt <= CAP) {
        rare_block(x, Wq, bq, Wk, bk, out, b, q, cnt, s_idx, s_mv);
    } else {
        if (t == 0) g_rlist[atomicAdd(&g_nrare, 1)] = row;
    }
}

// ---------------------------------------------------------------------------
// Kernel 2: verification + overflow cleanup (normally ~zero work).
// Verifies M* = (2*qb + 30)*1e-4 <= M0 with
// qb = (|Wq|_F xm + |bq|)(|Wk|_F xm + |bk|)/sqrt(8), xm = sqrt(g_xn2);
// every excluded key then carries < e^-30 relative softmax weight.
// Overflow rows (cnt > CAP) get an exact full-row pass (warp per (row,head)).
// If verification failed (never, for this data): exact recompute of ALL rows.
// Last block resets g_nrare for the next graph replay.
// ---------------------------------------------------------------------------
__global__ void __launch_bounds__(256) k_verify(
        const float* __restrict__ x, const float* __restrict__ mask,
        const float* __restrict__ Wq, const float* __restrict__ bq,
        const float* __restrict__ Wk, const float* __restrict__ bk,
        float* __restrict__ out) {
    __shared__ float s_part[8];
    __shared__ int   s_fb;

    int t    = threadIdx.x;
    int lane = t & 31;
    int w    = t >> 5;

    // parallel weight-norm reduction (all loads in flight at once)
    float wq2 = 0.f, wk2 = 0.f;
    if (t < 64) { float a = __ldg(Wq + t), c = __ldg(Wk + t); wq2 = a*a; wk2 = c*c; }
    float b2q = 0.f, b2k = 0.f;
    if (t < 8)  { float a = __ldg(bq + t), c = __ldg(bk + t); b2q = a*a; b2k = c*c; }
#pragma unroll
    for (int o = 16; o; o >>= 1) {
        wq2 += __shfl_xor_sync(0xffffffffu, wq2, o);
        wk2 += __shfl_xor_sync(0xffffffffu, wk2, o);
        b2q += __shfl_xor_sync(0xffffffffu, b2q, o);
        b2k += __shfl_xor_sync(0xffffffffu, b2k, o);
    }
    if (lane == 0 && w < 2) {
        s_part[w*4 + 0] = wq2; s_part[w*4 + 1] = wk2;
        s_part[w*4 + 2] = b2q; s_part[w*4 + 3] = b2k;
    }
    __syncthreads();
    if (t == 0) {
        float fq  = s_part[0] + s_part[4], fk  = s_part[1] + s_part[5];
        float nbq = s_part[2] + s_part[6], nbk = s_part[3] + s_part[7];
        float xm = sqrtf(__uint_as_float(g_xn2));
        float qb = (sqrtf(fq)*xm + sqrtf(nbq)) * (sqrtf(fk)*xm + sqrtf(nbk)) * 0.35355339059f;
        float mstar = (2.0f * qb + 30.0f) * 1e-4f;
        s_fb = (mstar > M0) ? 1 : 0;
    }
    __syncthreads();

    int fb    = s_fb;
    int ntask = (fb ? (BB * SS) : g_nrare) * HH;   // warp tasks
    int gw    = blockIdx.x * 8 + w;
    int nw    = VERIFY_BLOCKS * 8;

    for (int task = gw; task < ntask; task += nw) {
        int row = fb ? (task >> 3) : g_rlist[task >> 3];
        int h   = task & 7;
        int b   = row >> 11;
        int q   = row & (SS - 1);
        int bh  = b * HH + h;
        const float* xb = x + (size_t)bh * SS * DD;

        const float4* xq = (const float4*)(xb + (size_t)q * DD);
        float4 a0 = xq[0], a1 = xq[1];
        float xv[8] = {a0.x, a0.y, a0.z, a0.w, a1.x, a1.y, a1.z, a1.w};
        float qv[8];
#pragma unroll
        for (int i = 0; i < 8; i++) {
            float s = __ldg(bq + i);
#pragma unroll
            for (int j = 0; j < 8; j++) s += xv[j] * __ldg(Wq + i*8 + j);
            qv[i] = s;
        }

        // exact full-row online softmax, lanes stride keys
        const float* mrow = mask + (size_t)(b * SS + q) * SS;
        float m = -INFINITY, l = 0.f;
        float acc[8] = {0,0,0,0,0,0,0,0};
#pragma unroll 1
        for (int kk = lane; kk < SS; kk += 32) {
            const float4* xr = (const float4*)(xb + (size_t)kk * DD);
            float4 c0 = xr[0], c1 = xr[1];
            float xk[8] = {c0.x,c0.y,c0.z,c0.w,c1.x,c1.y,c1.z,c1.w};
            float sdot = 0.f;
#pragma unroll
            for (int i = 0; i < 8; i++) {
                float kv = __ldg(bk + i);
#pragma unroll
                for (int j = 0; j < 8; j++) kv += xk[j] * __ldg(Wk + i*8 + j);
                sdot += qv[i] * kv;
            }
            float sc = sdot * 0.35355339059f - 10000.0f * mrow[kk];
            float nm = fmaxf(m, sc);
            float corr = expf(m - nm);
            float p = expf(sc - nm);
            l = l * corr + p;
#pragma unroll
            for (int i = 0; i < 8; i++) acc[i] = acc[i]*corr + p*xk[i];
            m = nm;
        }
#pragma unroll
        for (int o = 16; o; o >>= 1) {
            float om = __shfl_xor_sync(0xffffffffu, m, o);
            float ol = __shfl_xor_sync(0xffffffffu, l, o);
            float oa[8];
#pragma unroll
            for (int i = 0; i < 8; i++) oa[i] = __shfl_xor_sync(0xffffffffu, acc[i], o);
            float nm = fmaxf(m, om);
            float c1 = expf(m - nm), c2 = expf(om - nm);
            l = l * c1 + ol * c2;
#pragma unroll
            for (int i = 0; i < 8; i++) acc[i] = acc[i]*c1 + oa[i]*c2;
            m = nm;
        }
        if (lane == 0) {
            float inv = 1.0f / l;
            float4* o = (float4*)(out + ((size_t)bh * SS + q) * DD);
            o[0] = make_float4(acc[0]*inv, acc[1]*inv, acc[2]*inv, acc[3]*inv);
            o[1] = make_float4(acc[4]*inv, acc[5]*inv, acc[6]*inv, acc[7]*inv);
        }
    }

    // last block resets per-call state for the next graph replay
    __syncthreads();
    if (t == 0) {
        __threadfence();
        int old = atomicAdd(&g_done2, 1);
        if (old == VERIFY_BLOCKS - 1) { g_nrare = 0; g_done2 = 0; }
    }
}

extern "C" void kernel_launch(void* const* d_in, const int* in_sizes, int n_in,
                              void* d_out, int out_size) {
    const float* x    = (const float*)d_in[0];  // [4,8,2048,8]
    const float* mask = (const float*)d_in[1];  // [4,1,2048,2048]
    const float* Wq   = (const float*)d_in[2];  // [8,8]
    const float* bq   = (const float*)d_in[3];  // [8]
    const float* Wk   = (const float*)d_in[4];  // [8,8]
    const float* bk   = (const float*)d_in[5];  // [8]
    float* out = (float*)d_out;                 // [4,8,2048,8]

    k_scan<<<BB*SS, 256>>>(x, mask, Wq, bq, Wk, bk, out);
    k_verify<<<VERIFY_BLOCKS, 256>>>(x, mask, Wq, bq, Wk, bk, out);
}